// round 12
// baseline (speedup 1.0000x reference)
#include <cuda_runtime.h>
#include <cstdint>
#include <cstddef>

#define BATCH 256
#define SEQ   512
#define HID   256
#define IN_DIM 65
#define RDIM  64

#define CLUSTER 8
#define HT 32                 // hidden units per CTA
#define BT 16                 // batch rows per cluster

#define OUT_N  ((size_t)BATCH * SEQ * RDIM)   //  8,388,608
#define HID_N  ((size_t)BATCH * SEQ * HID)    // 33,554,432
#define TOT_N  (OUT_N + HID_N)

// fallbacks so no global write can exceed d_out
__device__ float g_hid[HID_N];
__device__ float g_out[OUT_N];

// SMEM layout (floats)
#define OFF_WS 0          // [3][32][256]  rotated by 4u        24576
#define OFF_HQ 24576      // [2][16][256]  rotated by 4*(b>>1)   8192
#define OFF_WI 32768      // [3][32][66]                         6336
#define OFF_XS 39104      // [2][16][66]                         2112
#define OFF_WO 41216      // [8][256]                            2048
#define SM_FLOATS 43264
#define FUSED_SMEM (SM_FLOATS * 4)   // 173,056 B

__device__ __forceinline__ void ffma2(unsigned long long &acc,
                                      unsigned long long a, unsigned long long b) {
    asm("fma.rn.f32x2 %0, %1, %2, %0;" : "+l"(acc) : "l"(a), "l"(b));
}
__device__ __forceinline__ float f2sum(unsigned long long a) {
    unsigned int lo, hi;
    asm("mov.b64 {%0,%1}, %2;" : "=r"(lo), "=r"(hi) : "l"(a));
    return __uint_as_float(lo) + __uint_as_float(hi);
}
__device__ __forceinline__ float sigmoidf_(float x) {
    return __fdividef(1.0f, 1.0f + __expf(-x));
}

// head for timestep th: out[b][th][r] = relu(b_out[r] + sum_k Wout[r][k] h[b][k])
// thread: rw=tid>>5 (r), kq=(tid>>3)&3, bx=tid&7; k = 4j+kq  (banks kq+4bx: all 32 distinct)
__device__ __forceinline__ void head_step(
    const float* __restrict__ hb, const float* __restrict__ wo,
    float* __restrict__ out, int th, int b_base, int rg, float bo,
    int rw, int kq, int bx)
{
    const int b0 = 2 * bx, b1 = b0 + 1;
    const float* w = wo + rw * 256;
    const float* h0 = hb + b0 * 256;
    const float* h1 = hb + b1 * 256;
    const int rot = 4 * bx;
    float s0 = 0.f, s1 = 0.f;
#pragma unroll 8
    for (int j = 0; j < 64; ++j) {
        int k  = 4 * j + kq;
        int hk = (k + rot) & 255;
        float wv = w[k];
        s0 = fmaf(h0[hk], wv, s0);
        s1 = fmaf(h1[hk], wv, s1);
    }
    s0 += __shfl_xor_sync(0xffffffffu, s0, 8);
    s0 += __shfl_xor_sync(0xffffffffu, s0, 16);
    s1 += __shfl_xor_sync(0xffffffffu, s1, 8);
    s1 += __shfl_xor_sync(0xffffffffu, s1, 16);
    if (kq == 0) {
        out[((size_t)(b_base + b0) * SEQ + th) * RDIM + rg] = fmaxf(s0 + bo, 0.0f);
        out[((size_t)(b_base + b1) * SEQ + th) * RDIM + rg] = fmaxf(s1 + bo, 0.0f);
    }
}

__global__ void __cluster_dims__(CLUSTER, 1, 1) __launch_bounds__(256, 1)
fused_kernel(const float* __restrict__ stim,
             const float* __restrict__ W_ih,  const float* __restrict__ b_ih,
             const float* __restrict__ W_hh,  const float* __restrict__ b_hh,
             const float* __restrict__ W_out, const float* __restrict__ b_out,
             float* __restrict__ hid, float* __restrict__ out)
{
    extern __shared__ float sm[];
    float* Ws = sm + OFF_WS;
    float* hq = sm + OFF_HQ;
    float* wi = sm + OFF_WI;
    float* xs = sm + OFF_XS;
    float* wo = sm + OFF_WO;

    const int tid = threadIdx.x;
    unsigned int rank;
    asm("mov.u32 %0, %%cluster_ctarank;" : "=r"(rank));
    const int cl     = blockIdx.x >> 3;
    const int b_base = cl * BT;
    const int u_off  = (int)rank * HT;

    // ---- staging ----
    for (int idx = tid; idx < 3 * HT * HID; idx += 256) {
        int g = idx >> 13, rem = idx & 8191;
        int u = rem >> 8,  k   = rem & 255;
        Ws[(g * HT + u) * 256 + ((k + 4 * u) & 255)] =
            W_hh[((size_t)g * HID + u_off + u) * HID + k];
    }
    for (int idx = tid; idx < 3 * HT * IN_DIM; idx += 256) {
        int g = idx / (HT * IN_DIM), rem = idx % (HT * IN_DIM);
        int u = rem / IN_DIM,        k   = rem % IN_DIM;
        wi[(g * HT + u) * 66 + k] =
            W_ih[((size_t)g * HID + u_off + u) * IN_DIM + k];
    }
    for (int idx = tid; idx < 8 * HID; idx += 256)
        wo[idx] = W_out[(size_t)(rank * 8) * HID + idx];
    for (int idx = tid; idx < BT * HID; idx += 256)
        hq[idx] = 0.1f;                               // h[-1], rotation irrelevant
    for (int idx = tid; idx < BT * IN_DIM; idx += 256) {
        int b = idx / IN_DIM, k = idx % IN_DIM;
        xs[b * 66 + k] = stim[((size_t)(b_base + b) * SEQ) * IN_DIM + k];
    }
    __syncthreads();

    // ---- per-thread constants ----
    const int u  = tid >> 3;          // 0..31
    const int bx = tid & 7;           // 0..7
    const int b0 = 2 * bx, b1 = b0 + 1;
    const int ug = u_off + u;
    const int rw = tid >> 5;          // head r (warp id)
    const int kq = (tid >> 3) & 3;    // head k-quarter phase
    const int rg = (int)rank * 8 + rw;

    const float bhr = b_hh[ug],        bhz = b_hh[HID + ug],  bhn = b_hh[2 * HID + ug];
    const float bir = b_ih[ug],        biz = b_ih[HID + ug],  bin_ = b_ih[2 * HID + ug];
    const float bo  = b_out[rg];

    const float* wr = Ws + (0 * HT + u) * 256;
    const float* wz = Ws + (1 * HT + u) * 256;
    const float* wn = Ws + (2 * HT + u) * 256;
    const float* wir = wi + (0 * HT + u) * 66;
    const float* wiz = wi + (1 * HT + u) * 66;
    const float* win = wi + (2 * HT + u) * 66;

    float* ho0 = hid + (size_t)(b_base + b0) * SEQ * HID + ug;
    float* ho1 = hid + (size_t)(b_base + b1) * SEQ * HID + ug;

    const unsigned int hq_u32 = (unsigned int)__cvta_generic_to_shared(hq);
    const int wrot = 4 * u;           // W row rotation
    const int brot = 4 * bx;          // h row rotation (same for b0,b1)
    const int hsel = (ug + brot) & 255;

    int buf = 0;
    for (int t = 0; t < SEQ; ++t) {
        const float* hb = hq + buf * (BT * 256);

        // prefetch x[t+1] into regs (latency hidden by head+main+gi)
        float xr[5];
        if (t + 1 < SEQ) {
#pragma unroll
            for (int j = 0; j < 5; ++j) {
                int idx = tid + j * 256;
                if (idx < BT * IN_DIM) {
                    int b = idx / IN_DIM, k = idx % IN_DIM;
                    xr[j] = stim[((size_t)(b_base + b) * SEQ + (t + 1)) * IN_DIM + k];
                }
            }
        }

        // head for t-1 (h[t-1] = hb, complete since last barrier)
        if (t > 0)
            head_step(hb, wo, out, t - 1, b_base, rg, bo, rw, kq, bx);

        // ---- main recurrent dot:  gates_h = W_hh · h[t-1] ----
        unsigned long long ar0 = 0, az0 = 0, an0 = 0;
        unsigned long long ar1 = 0, az1 = 0, an1 = 0;
#pragma unroll 8
        for (int k4 = 0; k4 < 64; ++k4) {
            int wk = (4 * k4 + wrot) & 255;
            int hk = (4 * k4 + brot) & 255;
            ulonglong2 wrv = *(const ulonglong2*)(wr + wk);
            ulonglong2 wzv = *(const ulonglong2*)(wz + wk);
            ulonglong2 wnv = *(const ulonglong2*)(wn + wk);
            ulonglong2 h0v = *(const ulonglong2*)(hb + b0 * 256 + hk);
            ulonglong2 h1v = *(const ulonglong2*)(hb + b1 * 256 + hk);
            ffma2(ar0, h0v.x, wrv.x); ffma2(ar0, h0v.y, wrv.y);
            ffma2(az0, h0v.x, wzv.x); ffma2(az0, h0v.y, wzv.y);
            ffma2(an0, h0v.x, wnv.x); ffma2(an0, h0v.y, wnv.y);
            ffma2(ar1, h1v.x, wrv.x); ffma2(ar1, h1v.y, wrv.y);
            ffma2(az1, h1v.x, wzv.x); ffma2(az1, h1v.y, wzv.y);
            ffma2(an1, h1v.x, wnv.x); ffma2(an1, h1v.y, wnv.y);
        }

        // ---- gi = W_ih · x[t]  (x staged in xs[buf]) ----
        const float* x0p = xs + buf * (BT * 66) + b0 * 66;
        const float* x1p = x0p + 66;
        unsigned long long gr0 = 0, gz0 = 0, gn0 = 0;
        unsigned long long gr1 = 0, gz1 = 0, gn1 = 0;
#pragma unroll 8
        for (int j = 0; j < 32; ++j) {
            unsigned long long xv0 = *(const unsigned long long*)(x0p + 2 * j);
            unsigned long long xv1 = *(const unsigned long long*)(x1p + 2 * j);
            unsigned long long wrv = *(const unsigned long long*)(wir + 2 * j);
            unsigned long long wzv = *(const unsigned long long*)(wiz + 2 * j);
            unsigned long long wnv = *(const unsigned long long*)(win + 2 * j);
            ffma2(gr0, xv0, wrv); ffma2(gz0, xv0, wzv); ffma2(gn0, xv0, wnv);
            ffma2(gr1, xv1, wrv); ffma2(gz1, xv1, wzv); ffma2(gn1, xv1, wnv);
        }
        const float x0l = x0p[64], x1l = x1p[64];
        const float wrl = wir[64], wzl = wiz[64], wnl = win[64];

        float gir0 = f2sum(gr0) + x0l * wrl + bir;
        float giz0 = f2sum(gz0) + x0l * wzl + biz;
        float gin0 = f2sum(gn0) + x0l * wnl + bin_;
        float gir1 = f2sum(gr1) + x1l * wrl + bir;
        float giz1 = f2sum(gz1) + x1l * wzl + biz;
        float gin1 = f2sum(gn1) + x1l * wnl + bin_;

        float sr0 = f2sum(ar0) + bhr, sz0 = f2sum(az0) + bhz, sn0 = f2sum(an0) + bhn;
        float sr1 = f2sum(ar1) + bhr, sz1 = f2sum(az1) + bhz, sn1 = f2sum(an1) + bhn;

        float h_old0 = hb[b0 * 256 + hsel];
        float h_old1 = hb[b1 * 256 + hsel];

        float r0 = sigmoidf_(gir0 + sr0);
        float z0 = sigmoidf_(giz0 + sz0);
        float n0 = fmaxf(fmaf(r0, sn0, gin0), 0.0f);
        float hn0 = fmaf(z0, h_old0 - n0, n0);       // (1-z)n + z*h

        float r1 = sigmoidf_(gir1 + sr1);
        float z1 = sigmoidf_(giz1 + sz1);
        float n1 = fmaxf(fmaf(r1, sn1, gin1), 0.0f);
        float hn1 = fmaf(z1, h_old1 - n1, n1);

        ho0[0] = hn0;  ho0 += HID;
        ho1[0] = hn1;  ho1 += HID;

        const int nbuf = buf ^ 1;

        // stage x[t+1] into xs[nbuf]
        if (t + 1 < SEQ) {
#pragma unroll
            for (int j = 0; j < 5; ++j) {
                int idx = tid + j * 256;
                if (idx < BT * IN_DIM) {
                    int b = idx / IN_DIM, k = idx % IN_DIM;
                    xs[nbuf * (BT * 66) + b * 66 + k] = xr[j];
                }
            }
        }

        // broadcast hn into hq[nbuf] of ALL 8 cluster CTAs
        unsigned int a0 = hq_u32 + (unsigned int)((nbuf * (BT * 256) + b0 * 256 + hsel) * 4);
        unsigned int a1 = hq_u32 + (unsigned int)((nbuf * (BT * 256) + b1 * 256 + hsel) * 4);
#pragma unroll
        for (int rr = 0; rr < CLUSTER; ++rr) {
            unsigned int ra0, ra1;
            asm("mapa.shared::cluster.u32 %0, %1, %2;" : "=r"(ra0) : "r"(a0), "r"(rr));
            asm("mapa.shared::cluster.u32 %0, %1, %2;" : "=r"(ra1) : "r"(a1), "r"(rr));
            asm volatile("st.shared::cluster.f32 [%0], %1;" :: "r"(ra0), "f"(hn0) : "memory");
            asm volatile("st.shared::cluster.f32 [%0], %1;" :: "r"(ra1), "f"(hn1) : "memory");
        }
        asm volatile("barrier.cluster.arrive.aligned;" ::: "memory");
        asm volatile("barrier.cluster.wait.aligned;"   ::: "memory");

        buf = nbuf;
    }

    // head for t = 511
    head_step(hq + buf * (BT * 256), wo, out, SEQ - 1, b_base, rg, bo, rw, kq, bx);
}

// =====================================================================
extern "C" void kernel_launch(void* const* d_in, const int* in_sizes, int n_in,
                              void* d_out, int out_size)
{
    const float *stim = nullptr, *W_ih = nullptr, *W_hh = nullptr,
                *b_ih = nullptr, *b_hh = nullptr, *W_out = nullptr, *b_out = nullptr;

    for (int i = 0; i < n_in; ++i) {
        const float* p = (const float*)d_in[i];
        switch (in_sizes[i]) {
            case BATCH * SEQ * IN_DIM: stim  = p; break;
            case 3 * HID * IN_DIM:     W_ih  = p; break;
            case 3 * HID * HID:        W_hh  = p; break;
            case RDIM * HID:           W_out = p; break;
            case RDIM:                 b_out = p; break;
            case 3 * HID:
                if (!b_ih) b_ih = p; else b_hh = p;   // dict & alpha order agree
                break;
            default: break;
        }
    }
    if (!stim || !W_ih || !W_hh || !b_ih || !b_hh || !W_out || !b_out)
        return;

    float* g_hid_ptr;  cudaGetSymbolAddress((void**)&g_hid_ptr, g_hid);
    float* g_out_ptr;  cudaGetSymbolAddress((void**)&g_out_ptr, g_out);

    float* out;
    float* hid;
    if ((size_t)out_size >= TOT_N) {            // [out | rnn_hid]
        out = (float*)d_out;
        hid = (float*)d_out + OUT_N;
    } else if ((size_t)out_size >= HID_N) {
        hid = (float*)d_out;
        out = g_out_ptr;
    } else {
        out = (float*)d_out;
        hid = g_hid_ptr;
    }

    cudaFuncSetAttribute(fused_kernel, cudaFuncAttributeMaxDynamicSharedMemorySize, FUSED_SMEM);
    fused_kernel<<<(BATCH / BT) * CLUSTER, 256, FUSED_SMEM>>>(
        stim, W_ih, b_ih, W_hh, b_hh, W_out, b_out, hid, out);
}

// round 13
// speedup vs baseline: 1.7360x; 1.7360x over previous
#include <cuda_runtime.h>
#include <cstdint>
#include <cstddef>

#define BATCH 256
#define SEQ   512
#define HID   256
#define G3    768
#define IN_DIM 65
#define RDIM  64

#define OUT_N  ((size_t)BATCH * SEQ * RDIM)
#define HID_N  ((size_t)BATCH * SEQ * HID)
#define TOT_N  (OUT_N + HID_N)

__device__ float g_gi [(size_t)BATCH * SEQ * G3];  // 402 MB scratch
__device__ float g_hid[HID_N];
__device__ float g_out[OUT_N];

// ---------------- helpers ----------------
__device__ __forceinline__ void ffma2(unsigned long long &acc,
                                      unsigned long long a, unsigned long long b) {
    asm("fma.rn.f32x2 %0, %1, %2, %0;" : "+l"(acc) : "l"(a), "l"(b));
}
__device__ __forceinline__ float f2sum(unsigned long long a) {
    unsigned int lo, hi;
    asm("mov.b64 {%0,%1}, %2;" : "=r"(lo), "=r"(hi) : "l"(a));
    return __uint_as_float(lo) + __uint_as_float(hi);
}
__device__ __forceinline__ float sigmoidf_(float x) {
    return __fdividef(1.0f, 1.0f + __expf(-x));
}

// =====================================================================
// Kernel 1: gi = stimulus @ W_ih^T + b_ih  — R7 body, g-split for 2 CTA/SM
// =====================================================================
#define GI_TBT 16
#define GI_GBLK 384
#define GI_PITCH 70
#define GI_SMEM ((GI_GBLK * GI_PITCH + GI_TBT * GI_PITCH) * 4)   // 112,000 B

__global__ void __launch_bounds__(512, 2)
gi_kernel(const float* __restrict__ stim,
          const float* __restrict__ W_ih,
          const float* __restrict__ b_ih)
{
    extern __shared__ float sm[];
    float* w_s = sm;                       // [384][70]
    float* x_s = sm + GI_GBLK * GI_PITCH;  // [16][70]

    const int tid = threadIdx.x;
    const int bt0 = (blockIdx.x >> 1) * GI_TBT;
    const int g0  = (blockIdx.x & 1) * GI_GBLK;

    for (int idx = tid; idx < GI_GBLK * IN_DIM; idx += 512) {
        int g = idx / IN_DIM, k = idx - g * IN_DIM;
        w_s[g * GI_PITCH + k] = W_ih[(size_t)(g0 + g) * IN_DIM + k];
    }
    for (int idx = tid; idx < GI_TBT * IN_DIM; idx += 512) {
        int r = idx / IN_DIM, c = idx - r * IN_DIM;
        x_s[r * GI_PITCH + c] = stim[(size_t)(bt0 + r) * IN_DIM + c];
    }
    __syncthreads();

    const int gx = tid & 63;        // g_local = gx + 64*i, i < 6
    const int by = tid >> 6;        // bt rows 2by, 2by+1

    unsigned long long acc0[6], acc1[6];
#pragma unroll
    for (int i = 0; i < 6; ++i) { acc0[i] = 0ull; acc1[i] = 0ull; }

    const float* x0 = x_s + (2 * by) * GI_PITCH;
    const float* x1 = x_s + (2 * by + 1) * GI_PITCH;

#pragma unroll 8
    for (int k = 0; k < 64; k += 2) {
        unsigned long long xv0 = *(const unsigned long long*)(x0 + k);
        unsigned long long xv1 = *(const unsigned long long*)(x1 + k);
#pragma unroll
        for (int i = 0; i < 6; ++i) {
            unsigned long long wv =
                *(const unsigned long long*)(w_s + (gx + 64 * i) * GI_PITCH + k);
            ffma2(acc0[i], xv0, wv);
            ffma2(acc1[i], xv1, wv);
        }
    }
    const float x0l = x0[64], x1l = x1[64];

    const size_t base0 = (size_t)(bt0 + 2 * by) * G3 + g0;
    const size_t base1 = base0 + G3;
#pragma unroll
    for (int i = 0; i < 6; ++i) {
        int   gl   = gx + 64 * i;
        float w64  = w_s[gl * GI_PITCH + 64];
        float bias = b_ih[g0 + gl];
        g_gi[base0 + gl] = f2sum(acc0[i]) + x0l * w64 + bias;
        g_gi[base1 + gl] = f2sum(acc1[i]) + x1l * w64 + bias;
    }
}

// =====================================================================
// Kernel 2: GRU recurrence — 4-CTA cluster, 512 threads (1 batch row /
// thread, 4 warps/SMSP). Rotation layouts (conflict-free, no padding):
//   Ws[g][u][ (k+4u)&255 ]   196,608 B
//   hq[buf][b][ (k+4b)&255 ]  16,384 B
// Per-step sync: st.async + mbarrier complete_tx (no barrier.cluster).
// =====================================================================
#define CLUSTER 4
#define HT 64
#define BT 8
#define GRU_THREADS 512
#define MB_OFF 53248                       // float index of mbarriers
#define GRU_SMEM (53248 * 4 + 32)          // 212,992 + 2 mbarriers

__global__ void __cluster_dims__(CLUSTER, 1, 1) __launch_bounds__(GRU_THREADS, 1)
gru_kernel(const float* __restrict__ W_hh,
           const float* __restrict__ b_hh,
           float* __restrict__ out_hid)
{
    extern __shared__ float smem[];
    float* Ws = smem;                  // [3][64][256] rotated 4u
    float* hq = smem + 49152;          // [2][8][256]  rotated 4b
    unsigned long long* mb = (unsigned long long*)(smem + MB_OFF);

    const int tid = threadIdx.x;
    unsigned int rank;
    asm("mov.u32 %0, %%cluster_ctarank;" : "=r"(rank));
    const int cl     = blockIdx.x / CLUSTER;
    const int h_off  = (int)rank * HT;
    const int b_base = cl * BT;

    // stage W_hh slice with per-row rotation
    for (int idx = tid; idx < 3 * HT * HID; idx += GRU_THREADS) {
        int g = idx >> 14, rem = idx & 16383;
        int u = rem >> 8,  k   = rem & 255;
        Ws[(g * HT + u) * 256 + ((k + 4 * u) & 255)] =
            W_hh[((size_t)g * HID + h_off + u) * HID + k];
    }
    for (int idx = tid; idx < BT * 256; idx += GRU_THREADS)
        hq[idx] = 0.1f;                            // h[-1] (rotation irrelevant)
    if (tid == 0) {
        asm volatile("mbarrier.init.shared.b64 [%0], 1;" ::
                     "r"((unsigned)__cvta_generic_to_shared(mb))     : "memory");
        asm volatile("mbarrier.init.shared.b64 [%0], 1;" ::
                     "r"((unsigned)__cvta_generic_to_shared(mb + 1)) : "memory");
    }
    __syncthreads();
    // cluster-wide: peers' mbarrier init + hq init must be visible before
    // any st.async lands (one-time cost)
    asm volatile("barrier.cluster.arrive.aligned;" ::: "memory");
    asm volatile("barrier.cluster.wait.aligned;"   ::: "memory");

    const int u  = tid >> 3;          // 0..63
    const int b  = tid & 7;           // 0..7
    const int ug = h_off + u;
    const int hsel = (ug + 4 * b) & 255;

    const float bhr = b_hh[ug];
    const float bhz = b_hh[HID + ug];
    const float bhn = b_hh[2 * HID + ug];

    const float* gi_p = g_gi + (size_t)(b_base + b) * SEQ * G3 + ug;
    float*       ho   = out_hid + (size_t)(b_base + b) * SEQ * HID + ug;

    const float* wr = Ws + (0 * HT + u) * 256;
    const float* wz = Ws + (1 * HT + u) * 256;
    const float* wn = Ws + (2 * HT + u) * 256;
    const int wrot = 4 * u;
    const int brot = 4 * b;

    const unsigned hq_u32 = (unsigned)__cvta_generic_to_shared(hq);
    const unsigned mb_u32 = (unsigned)__cvta_generic_to_shared(mb);
    const unsigned TXB = BT * HID * 4;        // 8192 bytes per step per CTA

    // arm mb[1] for step-0 stores
    if (tid == 0)
        asm volatile("mbarrier.arrive.expect_tx.shared.b64 _, [%0], %1;"
                     :: "r"(mb_u32 + 8), "r"(TXB) : "memory");

    int buf = 0;
    int ph0 = 0, ph1 = 0;
    for (int t = 0; t < SEQ; ++t) {
        float gir = gi_p[0], giz = gi_p[HID], gin = gi_p[2 * HID];

        const float* hb = hq + buf * (BT * 256) + b * 256;
        float h_old = hb[hsel];

        unsigned long long ar = 0, az = 0, an = 0;
#pragma unroll 8
        for (int k4 = 0; k4 < 64; ++k4) {
            int wk = (4 * k4 + wrot) & 255;
            int hk = (4 * k4 + brot) & 255;
            ulonglong2 wrv = *(const ulonglong2*)(wr + wk);
            ulonglong2 wzv = *(const ulonglong2*)(wz + wk);
            ulonglong2 wnv = *(const ulonglong2*)(wn + wk);
            ulonglong2 hv  = *(const ulonglong2*)(hb + hk);
            ffma2(ar, hv.x, wrv.x); ffma2(ar, hv.y, wrv.y);
            ffma2(az, hv.x, wzv.x); ffma2(az, hv.y, wzv.y);
            ffma2(an, hv.x, wnv.x); ffma2(an, hv.y, wnv.y);
        }
        float sr = f2sum(ar) + bhr;
        float sz = f2sum(az) + bhz;
        float sn = f2sum(an) + bhn;

        float r = sigmoidf_(gir + sr);
        float z = sigmoidf_(giz + sz);
        float n = fmaxf(fmaf(r, sn, gin), 0.0f);
        float hn = fmaf(z, h_old - n, n);            // (1-z)n + z*h

        ho[0] = hn;

        if (t + 1 < SEQ) {
            const int nbuf = buf ^ 1;
            unsigned a  = hq_u32 + (unsigned)((nbuf * (BT * 256) + b * 256 + hsel) * 4);
            unsigned m  = mb_u32 + (unsigned)(nbuf * 8);
            unsigned hv = __float_as_uint(hn);
#pragma unroll
            for (int rr = 0; rr < CLUSTER; ++rr) {
                unsigned ra, rm;
                asm("mapa.shared::cluster.u32 %0, %1, %2;" : "=r"(ra) : "r"(a), "r"(rr));
                asm("mapa.shared::cluster.u32 %0, %1, %2;" : "=r"(rm) : "r"(m), "r"(rr));
                asm volatile(
                    "st.async.shared::cluster.mbarrier::complete_tx::bytes.b32 [%0], %1, [%2];"
                    :: "r"(ra), "r"(hv), "r"(rm) : "memory");
            }
            // wait: all 4 CTAs' stores into LOCAL hq[nbuf] complete
            {
                int p = (nbuf == 0) ? ph0 : ph1;
                unsigned done;
                asm volatile(
                    "{\n\t.reg .pred q;\n\t"
                    "mbarrier.try_wait.parity.acquire.cluster.shared::cta.b64 q, [%1], %2;\n\t"
                    "selp.b32 %0, 1, 0, q;\n\t}"
                    : "=r"(done) : "r"(m), "r"(p) : "memory");
                if (!done) {
                    asm volatile(
                        "{\n\t.reg .pred q;\n\t"
                        "W_%=:\n\t"
                        "mbarrier.try_wait.parity.acquire.cluster.shared::cta.b64 q, [%0], %1, 0x989680;\n\t"
                        "@q bra.uni D_%=;\n\t"
                        "bra.uni W_%=;\n\t"
                        "D_%=:\n\t}"
                        :: "r"(m), "r"(p) : "memory");
                }
                if (nbuf == 0) ph0 ^= 1; else ph1 ^= 1;
            }
            // arm mb[buf] for next step's stores
            if (tid == 0 && t + 2 < SEQ)
                asm volatile("mbarrier.arrive.expect_tx.shared.b64 _, [%0], %1;"
                             :: "r"(mb_u32 + (unsigned)(buf * 8)), "r"(TXB) : "memory");
            buf = nbuf;
        }
        gi_p += G3;  ho += HID;
    }
}

// =====================================================================
// Kernel 3: out = relu(rnn_hid @ W_out^T + b_out) — unchanged from R7.
// =====================================================================
#define HD_TBT 64
#define HD_HPITCH 260
#define HD_WPITCH 258
#define HD_SMEM ((HD_TBT * HD_HPITCH + RDIM * HD_WPITCH) * 4)

__global__ void __launch_bounds__(256, 1)
head_kernel(const float* __restrict__ hid,
            const float* __restrict__ W_out,
            const float* __restrict__ b_out,
            float* __restrict__ out)
{
    extern __shared__ float sm[];
    float* h_s = sm;
    float* w_s = sm + HD_TBT * HD_HPITCH;

    const int tid = threadIdx.x;
    const int bt0 = blockIdx.x * HD_TBT;

    for (int idx = tid; idx < HD_TBT * HID; idx += 256) {
        int r = idx >> 8, c = idx & 255;
        h_s[r * HD_HPITCH + c] = hid[(size_t)(bt0 + r) * HID + c];
    }
    for (int idx = tid; idx < RDIM * HID; idx += 256) {
        int r = idx >> 8, c = idx & 255;
        w_s[r * HD_WPITCH + c] = W_out[idx];
    }
    __syncthreads();

    const int rx = tid & 15;
    const int by = tid >> 4;

    unsigned long long acc[4][4];
#pragma unroll
    for (int j = 0; j < 4; ++j)
#pragma unroll
        for (int i = 0; i < 4; ++i) acc[j][i] = 0ull;

#pragma unroll 4
    for (int k = 0; k < HID; k += 2) {
        unsigned long long hv[4], wv[4];
#pragma unroll
        for (int j = 0; j < 4; ++j)
            hv[j] = *(const unsigned long long*)(h_s + (by * 4 + j) * HD_HPITCH + k);
#pragma unroll
        for (int i = 0; i < 4; ++i)
            wv[i] = *(const unsigned long long*)(w_s + (rx + 16 * i) * HD_WPITCH + k);
#pragma unroll
        for (int j = 0; j < 4; ++j)
#pragma unroll
            for (int i = 0; i < 4; ++i) ffma2(acc[j][i], hv[j], wv[i]);
    }

#pragma unroll
    for (int j = 0; j < 4; ++j) {
        size_t row = (size_t)(bt0 + by * 4 + j) * RDIM;
#pragma unroll
        for (int i = 0; i < 4; ++i) {
            int   r = rx + 16 * i;
            float v = f2sum(acc[j][i]) + b_out[r];
            out[row + r] = fmaxf(v, 0.0f);
        }
    }
}

// =====================================================================
extern "C" void kernel_launch(void* const* d_in, const int* in_sizes, int n_in,
                              void* d_out, int out_size)
{
    const float *stim = nullptr, *W_ih = nullptr, *W_hh = nullptr,
                *b_ih = nullptr, *b_hh = nullptr, *W_out = nullptr, *b_out = nullptr;

    for (int i = 0; i < n_in; ++i) {
        const float* p = (const float*)d_in[i];
        switch (in_sizes[i]) {
            case BATCH * SEQ * IN_DIM: stim  = p; break;
            case G3 * IN_DIM:          W_ih  = p; break;
            case G3 * HID:             W_hh  = p; break;
            case RDIM * HID:           W_out = p; break;
            case RDIM:                 b_out = p; break;
            case G3:
                if (!b_ih) b_ih = p; else b_hh = p;
                break;
            default: break;
        }
    }
    if (!stim || !W_ih || !W_hh || !b_ih || !b_hh || !W_out || !b_out)
        return;

    float* g_hid_ptr;  cudaGetSymbolAddress((void**)&g_hid_ptr, g_hid);
    float* g_out_ptr;  cudaGetSymbolAddress((void**)&g_out_ptr, g_out);

    float* out;
    float* hid;
    if ((size_t)out_size >= TOT_N) {
        out = (float*)d_out;
        hid = (float*)d_out + OUT_N;
    } else if ((size_t)out_size >= HID_N) {
        hid = (float*)d_out;
        out = g_out_ptr;
    } else {
        out = (float*)d_out;
        hid = g_hid_ptr;
    }

    cudaFuncSetAttribute(gi_kernel,   cudaFuncAttributeMaxDynamicSharedMemorySize, GI_SMEM);
    cudaFuncSetAttribute(gru_kernel,  cudaFuncAttributeMaxDynamicSharedMemorySize, GRU_SMEM);
    cudaFuncSetAttribute(head_kernel, cudaFuncAttributeMaxDynamicSharedMemorySize, HD_SMEM);

    gi_kernel  <<<(BATCH * SEQ / GI_TBT) * 2, 512, GI_SMEM>>>(stim, W_ih, b_ih);
    gru_kernel <<<(BATCH / BT) * CLUSTER, GRU_THREADS, GRU_SMEM>>>(W_hh, b_hh, hid);
    head_kernel<<<(BATCH * SEQ) / HD_TBT, 256, HD_SMEM>>>(hid, W_out, b_out, out);
}

// round 14
// speedup vs baseline: 1.7543x; 1.0106x over previous
#include <cuda_runtime.h>
#include <cstdint>
#include <cstddef>

#define BATCH 256
#define SEQ   512
#define HID   256
#define G3    768
#define IN_DIM 65
#define RDIM  64

#define OUT_N  ((size_t)BATCH * SEQ * RDIM)
#define HID_N  ((size_t)BATCH * SEQ * HID)
#define TOT_N  (OUT_N + HID_N)

__device__ float g_gi [(size_t)BATCH * SEQ * G3];  // 402 MB scratch
__device__ float g_hid[HID_N];
__device__ float g_out[OUT_N];

// ---------------- helpers ----------------
__device__ __forceinline__ void ffma2(unsigned long long &acc,
                                      unsigned long long a, unsigned long long b) {
    asm("fma.rn.f32x2 %0, %1, %2, %0;" : "+l"(acc) : "l"(a), "l"(b));
}
__device__ __forceinline__ float f2sum(unsigned long long a) {
    unsigned int lo, hi;
    asm("mov.b64 {%0,%1}, %2;" : "=r"(lo), "=r"(hi) : "l"(a));
    return __uint_as_float(lo) + __uint_as_float(hi);
}
__device__ __forceinline__ float sigmoidf_(float x) {
    return __fdividef(1.0f, 1.0f + __expf(-x));
}

// =====================================================================
// Kernel 1: gi = stimulus @ W_ih^T + b_ih — EXACT R7 version (729us).
// =====================================================================
#define GI_TBT 16
#define GI_PITCH 70
#define GI_SMEM ((G3 * GI_PITCH + GI_TBT * GI_PITCH) * 4)

__global__ void __launch_bounds__(512, 1)
gi_kernel(const float* __restrict__ stim,
          const float* __restrict__ W_ih,
          const float* __restrict__ b_ih)
{
    extern __shared__ float sm[];
    float* w_s = sm;                    // [768][70]
    float* x_s = sm + G3 * GI_PITCH;    // [16][70]

    const int tid = threadIdx.x;
    const int bt0 = blockIdx.x * GI_TBT;

    for (int idx = tid; idx < G3 * IN_DIM; idx += 512) {
        int g = idx / IN_DIM, k = idx - g * IN_DIM;
        w_s[g * GI_PITCH + k] = W_ih[idx];
    }
    for (int idx = tid; idx < GI_TBT * IN_DIM; idx += 512) {
        int r = idx / IN_DIM, c = idx - r * IN_DIM;
        x_s[r * GI_PITCH + c] = stim[(size_t)(bt0 + r) * IN_DIM + c];
    }
    __syncthreads();

    const int gx = tid & 63;
    const int by = tid >> 6;

    unsigned long long acc0[12], acc1[12];
#pragma unroll
    for (int i = 0; i < 12; ++i) { acc0[i] = 0ull; acc1[i] = 0ull; }

    const float* x0 = x_s + (by * 2) * GI_PITCH;
    const float* x1 = x_s + (by * 2 + 1) * GI_PITCH;

#pragma unroll 4
    for (int k = 0; k < 64; k += 2) {
        unsigned long long xv0 = *(const unsigned long long*)(x0 + k);
        unsigned long long xv1 = *(const unsigned long long*)(x1 + k);
#pragma unroll
        for (int i = 0; i < 12; ++i) {
            unsigned long long wv =
                *(const unsigned long long*)(w_s + (gx + 64 * i) * GI_PITCH + k);
            ffma2(acc0[i], xv0, wv);
            ffma2(acc1[i], xv1, wv);
        }
    }
    const float x0l = x0[64], x1l = x1[64];

    const size_t base0 = (size_t)(bt0 + by * 2) * G3;
    const size_t base1 = base0 + G3;
#pragma unroll
    for (int i = 0; i < 12; ++i) {
        int   g    = gx + 64 * i;
        float w64  = w_s[g * GI_PITCH + 64];
        float bias = b_ih[g];
        g_gi[base0 + g] = f2sum(acc0[i]) + x0l * w64 + bias;
        g_gi[base1 + g] = f2sum(acc1[i]) + x1l * w64 + bias;
    }
}

// =====================================================================
// Kernel 2: GRU — R7 layout (padded pitch 260, affine addressing,
// barrier.cluster) but 512 threads, 1 batch row/thread -> 4 warps/SMSP.
// =====================================================================
#define CLUSTER 4
#define HT 64
#define BT 8
#define WPITCH 260
#define HPITCH 260
#define GRU_THREADS 512
#define GRU_SMEM ((3 * HT * WPITCH + 2 * BT * HPITCH) * 4)   // 216,320 B

__global__ void __cluster_dims__(CLUSTER, 1, 1) __launch_bounds__(GRU_THREADS, 1)
gru_kernel(const float* __restrict__ W_hh,
           const float* __restrict__ b_hh,
           float* __restrict__ out_hid)
{
    extern __shared__ float smem[];
    float* Ws = smem;                   // [3][64][260]
    float* hs = smem + 3 * HT * WPITCH; // [2][8][260]

    const int tid = threadIdx.x;
    unsigned int rank;
    asm("mov.u32 %0, %%cluster_ctarank;" : "=r"(rank));
    const int cl     = blockIdx.x / CLUSTER;
    const int h_off  = (int)rank * HT;
    const int b_base = cl * BT;

    for (int idx = tid; idx < 3 * HT * HID; idx += GRU_THREADS) {
        int g   = idx >> 14;
        int rem = idx & 16383;
        int u   = rem >> 8;
        int k   = rem & 255;
        Ws[(g * HT + u) * WPITCH + k] = W_hh[((g * HID) + h_off + u) * HID + k];
    }
    for (int idx = tid; idx < BT * HID; idx += GRU_THREADS) {
        int b = idx >> 8, c = idx & 255;
        hs[b * HPITCH + c] = 0.1f;                  // buf0 only
    }
    __syncthreads();

    const int u  = tid >> 3;          // 0..63
    const int b  = tid & 7;           // 0..7
    const int ug = h_off + u;

    const float bhr = b_hh[ug];
    const float bhz = b_hh[HID + ug];
    const float bhn = b_hh[2 * HID + ug];

    const float* gi_p = g_gi + (size_t)(b_base + b) * SEQ * G3 + ug;
    float*       ho   = out_hid + (size_t)(b_base + b) * SEQ * HID + ug;

    const unsigned int hs_u32 = (unsigned int)__cvta_generic_to_shared(hs);

    const float* w_r = Ws + (0 * HT + u) * WPITCH;
    const float* w_z = Ws + (1 * HT + u) * WPITCH;
    const float* w_n = Ws + (2 * HT + u) * WPITCH;

    int buf = 0;
    for (int t = 0; t < SEQ; ++t) {
        // prefetch gi: consumed only after the ~3K-cycle dot loop
        float gir = gi_p[0], giz = gi_p[HID], gin = gi_p[2 * HID];

        const float* hr = hs + (buf * BT + b) * HPITCH;

        unsigned long long ar = 0, az = 0, an = 0;
#pragma unroll 8
        for (int k = 0; k < HID; k += 4) {
            ulonglong2 hv = *(const ulonglong2*)(hr + k);
            ulonglong2 wr = *(const ulonglong2*)(w_r + k);
            ulonglong2 wz = *(const ulonglong2*)(w_z + k);
            ulonglong2 wn = *(const ulonglong2*)(w_n + k);
            ffma2(ar, hv.x, wr.x); ffma2(ar, hv.y, wr.y);
            ffma2(az, hv.x, wz.x); ffma2(az, hv.y, wz.y);
            ffma2(an, hv.x, wn.x); ffma2(an, hv.y, wn.y);
        }
        float sr = f2sum(ar) + bhr;
        float sz = f2sum(az) + bhz;
        float sn = f2sum(an) + bhn;

        float h_old = hr[ug];

        float r = sigmoidf_(gir + sr);
        float z = sigmoidf_(giz + sz);
        float n = fmaxf(fmaf(r, sn, gin), 0.0f);
        float hn = fmaf(z, h_old - n, n);            // (1-z)n + z*h

        // broadcast new h into next buffer of ALL cluster CTAs (incl. self)
        const int nbuf = buf ^ 1;
        unsigned int a = hs_u32 +
            (unsigned int)(((nbuf * BT + b) * HPITCH + ug) * 4);
#pragma unroll
        for (int rr = 0; rr < CLUSTER; ++rr) {
            unsigned int ra;
            asm("mapa.shared::cluster.u32 %0, %1, %2;" : "=r"(ra) : "r"(a), "r"(rr));
            asm volatile("st.shared::cluster.f32 [%0], %1;" :: "r"(ra), "f"(hn) : "memory");
        }
        asm volatile("barrier.cluster.arrive.aligned;" ::: "memory");

        // hide part of barrier latency behind the global store
        ho[0] = hn;

        asm volatile("barrier.cluster.wait.aligned;" ::: "memory");

        buf = nbuf;
        gi_p += G3;  ho += HID;
    }
}

// =====================================================================
// Kernel 3: out = relu(rnn_hid @ W_out^T + b_out) — unchanged.
// =====================================================================
#define HD_TBT 64
#define HD_HPITCH 260
#define HD_WPITCH 258
#define HD_SMEM ((HD_TBT * HD_HPITCH + RDIM * HD_WPITCH) * 4)

__global__ void __launch_bounds__(256, 1)
head_kernel(const float* __restrict__ hid,
            const float* __restrict__ W_out,
            const float* __restrict__ b_out,
            float* __restrict__ out)
{
    extern __shared__ float sm[];
    float* h_s = sm;
    float* w_s = sm + HD_TBT * HD_HPITCH;

    const int tid = threadIdx.x;
    const int bt0 = blockIdx.x * HD_TBT;

    for (int idx = tid; idx < HD_TBT * HID; idx += 256) {
        int r = idx >> 8, c = idx & 255;
        h_s[r * HD_HPITCH + c] = hid[(size_t)(bt0 + r) * HID + c];
    }
    for (int idx = tid; idx < RDIM * HID; idx += 256) {
        int r = idx >> 8, c = idx & 255;
        w_s[r * HD_WPITCH + c] = W_out[idx];
    }
    __syncthreads();

    const int rx = tid & 15;
    const int by = tid >> 4;

    unsigned long long acc[4][4];
#pragma unroll
    for (int j = 0; j < 4; ++j)
#pragma unroll
        for (int i = 0; i < 4; ++i) acc[j][i] = 0ull;

#pragma unroll 4
    for (int k = 0; k < HID; k += 2) {
        unsigned long long hv[4], wv[4];
#pragma unroll
        for (int j = 0; j < 4; ++j)
            hv[j] = *(const unsigned long long*)(h_s + (by * 4 + j) * HD_HPITCH + k);
#pragma unroll
        for (int i = 0; i < 4; ++i)
            wv[i] = *(const unsigned long long*)(w_s + (rx + 16 * i) * HD_WPITCH + k);
#pragma unroll
        for (int j = 0; j < 4; ++j)
#pragma unroll
            for (int i = 0; i < 4; ++i) ffma2(acc[j][i], hv[j], wv[i]);
    }

#pragma unroll
    for (int j = 0; j < 4; ++j) {
        size_t row = (size_t)(bt0 + by * 4 + j) * RDIM;
#pragma unroll
        for (int i = 0; i < 4; ++i) {
            int   r = rx + 16 * i;
            float v = f2sum(acc[j][i]) + b_out[r];
            out[row + r] = fmaxf(v, 0.0f);
        }
    }
}

// =====================================================================
extern "C" void kernel_launch(void* const* d_in, const int* in_sizes, int n_in,
                              void* d_out, int out_size)
{
    const float *stim = nullptr, *W_ih = nullptr, *W_hh = nullptr,
                *b_ih = nullptr, *b_hh = nullptr, *W_out = nullptr, *b_out = nullptr;

    for (int i = 0; i < n_in; ++i) {
        const float* p = (const float*)d_in[i];
        switch (in_sizes[i]) {
            case BATCH * SEQ * IN_DIM: stim  = p; break;
            case G3 * IN_DIM:          W_ih  = p; break;
            case G3 * HID:             W_hh  = p; break;
            case RDIM * HID:           W_out = p; break;
            case RDIM:                 b_out = p; break;
            case G3:
                if (!b_ih) b_ih = p; else b_hh = p;
                break;
            default: break;
        }
    }
    if (!stim || !W_ih || !W_hh || !b_ih || !b_hh || !W_out || !b_out)
        return;

    float* g_hid_ptr;  cudaGetSymbolAddress((void**)&g_hid_ptr, g_hid);
    float* g_out_ptr;  cudaGetSymbolAddress((void**)&g_out_ptr, g_out);

    float* out;
    float* hid;
    if ((size_t)out_size >= TOT_N) {
        out = (float*)d_out;
        hid = (float*)d_out + OUT_N;
    } else if ((size_t)out_size >= HID_N) {
        hid = (float*)d_out;
        out = g_out_ptr;
    } else {
        out = (float*)d_out;
        hid = g_hid_ptr;
    }

    cudaFuncSetAttribute(gi_kernel,   cudaFuncAttributeMaxDynamicSharedMemorySize, GI_SMEM);
    cudaFuncSetAttribute(gru_kernel,  cudaFuncAttributeMaxDynamicSharedMemorySize, GRU_SMEM);
    cudaFuncSetAttribute(head_kernel, cudaFuncAttributeMaxDynamicSharedMemorySize, HD_SMEM);

    gi_kernel  <<<(BATCH * SEQ) / GI_TBT, 512, GI_SMEM>>>(stim, W_ih, b_ih);
    gru_kernel <<<(BATCH / BT) * CLUSTER, GRU_THREADS, GRU_SMEM>>>(W_hh, b_hh, hid);
    head_kernel<<<(BATCH * SEQ) / HD_TBT, 256, HD_SMEM>>>(hid, W_out, b_out, out);
}

// round 15
// speedup vs baseline: 2.1570x; 1.2295x over previous
#include <cuda_runtime.h>
#include <cstdint>
#include <cstddef>

#define BATCH 256
#define SEQ   512
#define HID   256
#define G3    768
#define IN_DIM 65
#define RDIM  64

#define OUT_N  ((size_t)BATCH * SEQ * RDIM)
#define HID_N  ((size_t)BATCH * SEQ * HID)
#define TOT_N  (OUT_N + HID_N)

__device__ float g_gi [(size_t)BATCH * SEQ * G3];  // 402 MB scratch
__device__ float g_hid[HID_N];
__device__ float g_out[OUT_N];

// ---------------- helpers ----------------
__device__ __forceinline__ void ffma2(unsigned long long &acc,
                                      unsigned long long a, unsigned long long b) {
    asm("fma.rn.f32x2 %0, %1, %2, %0;" : "+l"(acc) : "l"(a), "l"(b));
}
__device__ __forceinline__ float f2sum(unsigned long long a) {
    unsigned int lo, hi;
    asm("mov.b64 {%0,%1}, %2;" : "=r"(lo), "=r"(hi) : "l"(a));
    return __uint_as_float(lo) + __uint_as_float(hi);
}
__device__ __forceinline__ float sigmoidf_(float x) {
    return __fdividef(1.0f, 1.0f + __expf(-x));
}

// =====================================================================
// Kernel 1: gi = stimulus @ W_ih^T + b_ih — R7 body, ONE change:
// lane mapping swapped (gx = tid>>3, by = tid&7) so w-loads are 4 rows
// x 8-way broadcast (1 wf) and x-loads 8 rows x 4-way broadcast (1 wf),
// instead of 32 consecutive rows at 2-way bank conflict (4 wf).
// =====================================================================
#define GI_TBT 16
#define GI_PITCH 70
#define GI_SMEM ((G3 * GI_PITCH + GI_TBT * GI_PITCH) * 4)

__global__ void __launch_bounds__(512, 1)
gi_kernel(const float* __restrict__ stim,
          const float* __restrict__ W_ih,
          const float* __restrict__ b_ih)
{
    extern __shared__ float sm[];
    float* w_s = sm;                    // [768][70]
    float* x_s = sm + G3 * GI_PITCH;    // [16][70]

    const int tid = threadIdx.x;
    const int bt0 = blockIdx.x * GI_TBT;

    for (int idx = tid; idx < G3 * IN_DIM; idx += 512) {
        int g = idx / IN_DIM, k = idx - g * IN_DIM;
        w_s[g * GI_PITCH + k] = W_ih[idx];
    }
    for (int idx = tid; idx < GI_TBT * IN_DIM; idx += 512) {
        int r = idx / IN_DIM, c = idx - r * IN_DIM;
        x_s[r * GI_PITCH + c] = stim[(size_t)(bt0 + r) * IN_DIM + c];
    }
    __syncthreads();

    const int gx = tid >> 3;        // 0..63  (4 distinct per warp -> bcast w)
    const int by = tid & 7;         // 0..7   (lane-varying -> distinct x rows)

    unsigned long long acc0[12], acc1[12];
#pragma unroll
    for (int i = 0; i < 12; ++i) { acc0[i] = 0ull; acc1[i] = 0ull; }

    const float* x0 = x_s + (by * 2) * GI_PITCH;
    const float* x1 = x_s + (by * 2 + 1) * GI_PITCH;

#pragma unroll 4
    for (int k = 0; k < 64; k += 2) {
        unsigned long long xv0 = *(const unsigned long long*)(x0 + k);
        unsigned long long xv1 = *(const unsigned long long*)(x1 + k);
#pragma unroll
        for (int i = 0; i < 12; ++i) {
            unsigned long long wv =
                *(const unsigned long long*)(w_s + (gx + 64 * i) * GI_PITCH + k);
            ffma2(acc0[i], xv0, wv);
            ffma2(acc1[i], xv1, wv);
        }
    }
    const float x0l = x0[64], x1l = x1[64];

    const size_t base0 = (size_t)(bt0 + by * 2) * G3;
    const size_t base1 = base0 + G3;
#pragma unroll
    for (int i = 0; i < 12; ++i) {
        int   g    = gx + 64 * i;
        float w64  = w_s[g * GI_PITCH + 64];
        float bias = b_ih[g];
        g_gi[base0 + g] = f2sum(acc0[i]) + x0l * w64 + bias;
        g_gi[base1 + g] = f2sum(acc1[i]) + x1l * w64 + bias;
    }
}

// =====================================================================
// Probe: empty kernel between gi and gru to shift the fixed ncu capture
// slot onto gru_kernel.
// =====================================================================
__global__ void probe_kernel() {}

// =====================================================================
// Kernel 2: GRU — EXACT R7 version (best measured) + STG moved between
// cluster arrive and wait.
// =====================================================================
#define CLUSTER 4
#define HT 64
#define BT 8
#define WPITCH 260
#define HPITCH 260
#define GRU_SMEM ((3 * HT * WPITCH + 2 * BT * HPITCH) * 4)

__global__ void __cluster_dims__(CLUSTER, 1, 1) __launch_bounds__(256, 1)
gru_kernel(const float* __restrict__ W_hh,
           const float* __restrict__ b_hh,
           float* __restrict__ out_hid)
{
    extern __shared__ float smem[];
    float* Ws = smem;                   // [3][64][260]
    float* hs = smem + 3 * HT * WPITCH; // [2][8][260]

    const int tid = threadIdx.x;
    unsigned int rank;
    asm("mov.u32 %0, %%cluster_ctarank;" : "=r"(rank));
    const int cl     = blockIdx.x / CLUSTER;
    const int h_off  = (int)rank * HT;
    const int b_base = cl * BT;

    for (int idx = tid; idx < 3 * HT * HID; idx += 256) {
        int g   = idx >> 14;
        int rem = idx & 16383;
        int u   = rem >> 8;
        int k   = rem & 255;
        Ws[(g * HT + u) * WPITCH + k] = W_hh[((g * HID) + h_off + u) * HID + k];
    }
    for (int idx = tid; idx < BT * HID; idx += 256) {
        int b = idx >> 8, c = idx & 255;
        hs[b * HPITCH + c] = 0.1f;
    }
    __syncthreads();

    const int bx = tid & 3;
    const int u  = tid >> 2;
    const int b0 = 2 * bx, b1 = 2 * bx + 1;
    const int ug = h_off + u;

    const float bhr = b_hh[ug];
    const float bhz = b_hh[HID + ug];
    const float bhn = b_hh[2 * HID + ug];

    const float* gi0 = g_gi + (size_t)(b_base + b0) * SEQ * G3 + ug;
    const float* gi1 = g_gi + (size_t)(b_base + b1) * SEQ * G3 + ug;
    float* o0 = out_hid + (size_t)(b_base + b0) * SEQ * HID + ug;
    float* o1 = out_hid + (size_t)(b_base + b1) * SEQ * HID + ug;

    const unsigned int hs_u32 = (unsigned int)__cvta_generic_to_shared(hs);

    const float* w_r = Ws + (0 * HT + u) * WPITCH;
    const float* w_z = Ws + (1 * HT + u) * WPITCH;
    const float* w_n = Ws + (2 * HT + u) * WPITCH;

    int buf = 0;
    for (int t = 0; t < SEQ; ++t) {
        float gir0 = gi0[0], giz0 = gi0[HID], gin0 = gi0[2 * HID];
        float gir1 = gi1[0], giz1 = gi1[HID], gin1 = gi1[2 * HID];

        const float* hr0 = hs + (buf * BT + b0) * HPITCH;
        const float* hr1 = hs + (buf * BT + b1) * HPITCH;

        unsigned long long ar0 = 0, az0 = 0, an0 = 0;
        unsigned long long ar1 = 0, az1 = 0, an1 = 0;
#pragma unroll 8
        for (int k = 0; k < HID; k += 4) {
            ulonglong2 h0 = *(const ulonglong2*)(hr0 + k);
            ulonglong2 h1 = *(const ulonglong2*)(hr1 + k);
            ulonglong2 wr = *(const ulonglong2*)(w_r + k);
            ulonglong2 wz = *(const ulonglong2*)(w_z + k);
            ulonglong2 wn = *(const ulonglong2*)(w_n + k);
            ffma2(ar0, h0.x, wr.x); ffma2(ar0, h0.y, wr.y);
            ffma2(az0, h0.x, wz.x); ffma2(az0, h0.y, wz.y);
            ffma2(an0, h0.x, wn.x); ffma2(an0, h0.y, wn.y);
            ffma2(ar1, h1.x, wr.x); ffma2(ar1, h1.y, wr.y);
            ffma2(az1, h1.x, wz.x); ffma2(az1, h1.y, wz.y);
            ffma2(an1, h1.x, wn.x); ffma2(an1, h1.y, wn.y);
        }
        float sr0 = f2sum(ar0) + bhr, sz0 = f2sum(az0) + bhz, sn0 = f2sum(an0) + bhn;
        float sr1 = f2sum(ar1) + bhr, sz1 = f2sum(az1) + bhz, sn1 = f2sum(an1) + bhn;

        float h_old0 = hr0[ug];
        float h_old1 = hr1[ug];

        float r0 = sigmoidf_(gir0 + sr0);
        float z0 = sigmoidf_(giz0 + sz0);
        float n0 = fmaxf(fmaf(r0, sn0, gin0), 0.0f);
        float hn0 = fmaf(z0, h_old0 - n0, n0);      // (1-z)n + z*h

        float r1 = sigmoidf_(gir1 + sr1);
        float z1 = sigmoidf_(giz1 + sz1);
        float n1 = fmaxf(fmaf(r1, sn1, gin1), 0.0f);
        float hn1 = fmaf(z1, h_old1 - n1, n1);

        const int nbuf = buf ^ 1;
        unsigned int a0 = hs_u32 + (unsigned int)(((nbuf * BT + b0) * HPITCH + ug) * 4);
        unsigned int a1 = hs_u32 + (unsigned int)(((nbuf * BT + b1) * HPITCH + ug) * 4);
#pragma unroll
        for (int rr = 0; rr < CLUSTER; ++rr) {
            unsigned int ra0, ra1;
            asm("mapa.shared::cluster.u32 %0, %1, %2;" : "=r"(ra0) : "r"(a0), "r"(rr));
            asm("mapa.shared::cluster.u32 %0, %1, %2;" : "=r"(ra1) : "r"(a1), "r"(rr));
            asm volatile("st.shared::cluster.f32 [%0], %1;" :: "r"(ra0), "f"(hn0) : "memory");
            asm volatile("st.shared::cluster.f32 [%0], %1;" :: "r"(ra1), "f"(hn1) : "memory");
        }
        asm volatile("barrier.cluster.arrive.aligned;" ::: "memory");

        // hide STG issue behind the cluster barrier
        o0[0] = hn0;
        o1[0] = hn1;

        asm volatile("barrier.cluster.wait.aligned;" ::: "memory");

        buf = nbuf;
        gi0 += G3; gi1 += G3; o0 += HID; o1 += HID;
    }
}

// =====================================================================
// Kernel 3: out = relu(rnn_hid @ W_out^T + b_out) — unchanged.
// =====================================================================
#define HD_TBT 64
#define HD_HPITCH 260
#define HD_WPITCH 258
#define HD_SMEM ((HD_TBT * HD_HPITCH + RDIM * HD_WPITCH) * 4)

__global__ void __launch_bounds__(256, 1)
head_kernel(const float* __restrict__ hid,
            const float* __restrict__ W_out,
            const float* __restrict__ b_out,
            float* __restrict__ out)
{
    extern __shared__ float sm[];
    float* h_s = sm;
    float* w_s = sm + HD_TBT * HD_HPITCH;

    const int tid = threadIdx.x;
    const int bt0 = blockIdx.x * HD_TBT;

    for (int idx = tid; idx < HD_TBT * HID; idx += 256) {
        int r = idx >> 8, c = idx & 255;
        h_s[r * HD_HPITCH + c] = hid[(size_t)(bt0 + r) * HID + c];
    }
    for (int idx = tid; idx < RDIM * HID; idx += 256) {
        int r = idx >> 8, c = idx & 255;
        w_s[r * HD_WPITCH + c] = W_out[idx];
    }
    __syncthreads();

    const int rx = tid & 15;
    const int by = tid >> 4;

    unsigned long long acc[4][4];
#pragma unroll
    for (int j = 0; j < 4; ++j)
#pragma unroll
        for (int i = 0; i < 4; ++i) acc[j][i] = 0ull;

#pragma unroll 4
    for (int k = 0; k < HID; k += 2) {
        unsigned long long hv[4], wv[4];
#pragma unroll
        for (int j = 0; j < 4; ++j)
            hv[j] = *(const unsigned long long*)(h_s + (by * 4 + j) * HD_HPITCH + k);
#pragma unroll
        for (int i = 0; i < 4; ++i)
            wv[i] = *(const unsigned long long*)(w_s + (rx + 16 * i) * HD_WPITCH + k);
#pragma unroll
        for (int j = 0; j < 4; ++j)
#pragma unroll
            for (int i = 0; i < 4; ++i) ffma2(acc[j][i], hv[j], wv[i]);
    }

#pragma unroll
    for (int j = 0; j < 4; ++j) {
        size_t row = (size_t)(bt0 + by * 4 + j) * RDIM;
#pragma unroll
        for (int i = 0; i < 4; ++i) {
            int   r = rx + 16 * i;
            float v = f2sum(acc[j][i]) + b_out[r];
            out[row + r] = fmaxf(v, 0.0f);
        }
    }
}

// =====================================================================
extern "C" void kernel_launch(void* const* d_in, const int* in_sizes, int n_in,
                              void* d_out, int out_size)
{
    const float *stim = nullptr, *W_ih = nullptr, *W_hh = nullptr,
                *b_ih = nullptr, *b_hh = nullptr, *W_out = nullptr, *b_out = nullptr;

    for (int i = 0; i < n_in; ++i) {
        const float* p = (const float*)d_in[i];
        switch (in_sizes[i]) {
            case BATCH * SEQ * IN_DIM: stim  = p; break;
            case G3 * IN_DIM:          W_ih  = p; break;
            case G3 * HID:             W_hh  = p; break;
            case RDIM * HID:           W_out = p; break;
            case RDIM:                 b_out = p; break;
            case G3:
                if (!b_ih) b_ih = p; else b_hh = p;
                break;
            default: break;
        }
    }
    if (!stim || !W_ih || !W_hh || !b_ih || !b_hh || !W_out || !b_out)
        return;

    float* g_hid_ptr;  cudaGetSymbolAddress((void**)&g_hid_ptr, g_hid);
    float* g_out_ptr;  cudaGetSymbolAddress((void**)&g_out_ptr, g_out);

    float* out;
    float* hid;
    if ((size_t)out_size >= TOT_N) {
        out = (float*)d_out;
        hid = (float*)d_out + OUT_N;
    } else if ((size_t)out_size >= HID_N) {
        hid = (float*)d_out;
        out = g_out_ptr;
    } else {
        out = (float*)d_out;
        hid = g_hid_ptr;
    }

    cudaFuncSetAttribute(gi_kernel,   cudaFuncAttributeMaxDynamicSharedMemorySize, GI_SMEM);
    cudaFuncSetAttribute(gru_kernel,  cudaFuncAttributeMaxDynamicSharedMemorySize, GRU_SMEM);
    cudaFuncSetAttribute(head_kernel, cudaFuncAttributeMaxDynamicSharedMemorySize, HD_SMEM);

    gi_kernel  <<<(BATCH * SEQ) / GI_TBT, 512, GI_SMEM>>>(stim, W_ih, b_ih);
    probe_kernel<<<1, 32>>>();   // shifts ncu capture slot toward gru_kernel
    gru_kernel <<<(BATCH / BT) * CLUSTER, 256, GRU_SMEM>>>(W_hh, b_hh, hid);
    head_kernel<<<(BATCH * SEQ) / HD_TBT, 256, HD_SMEM>>>(hid, W_out, b_out, out);
}